// round 7
// baseline (speedup 1.0000x reference)
#include <cuda_runtime.h>
#include <math.h>

#define T_DATA   50000
#define E_NO     1000
#define I_NO     200
#define SUB_NO   20
#define H_NO     16
#define T_NO     200
#define COS_NO   20

#define S_PITCH  50432
#define CONV_TT  512
#define PI_F     3.14159265358979323846f
#define HALF_PI_F 1.57079632679489662f

typedef unsigned long long ull;

__device__ __forceinline__ ull pack2(float lo, float hi) {
    ull r; asm("mov.b64 %0, {%1, %2};" : "=l"(r) : "f"(lo), "f"(hi)); return r;
}
__device__ __forceinline__ void fma2(ull& d, ull a, ull b) {
    asm("fma.rn.f32x2 %0, %1, %2, %0;" : "+l"(d) : "l"(a), "l"(b));
}
__device__ __forceinline__ float2 unpack2(ull v) {
    float2 f; asm("mov.b64 {%0, %1}, %2;" : "=f"(f.x), "=f"(f.y) : "l"(v)); return f;
}

// ---------------- device scratch ----------------
__device__ float g_S[2 * SUB_NO * S_PITCH];          // [40][S_PITCH], pad 199 zeros
__device__ float g_kern2[SUB_NO * 2 * H_NO * T_NO];  // [s][c][h/2][d][h%2]
__device__ float g_partial[SUB_NO * T_DATA];

// ---------------- merged: basis*W_conv (+ flipped copy) AND g_S pad zeroing ----------------
#define BASIS_ITEMS (SUB_NO * H_NO * 2 * T_NO)       // 128000 -> 500 blocks of 256
#define BASIS_BLOCKS 500
#define ZERO_PER_CH (199 + (S_PITCH - (199 + T_DATA)))   // 432
#define ZERO_ITEMS (2 * SUB_NO * ZERO_PER_CH)
#define ZERO_BLOCKS ((ZERO_ITEMS + 255) / 256)

__global__ void prep_kernel(const float* __restrict__ W_conv,
                            float* __restrict__ out_kern /* may be null */) {
    int bid = blockIdx.x;
    if (bid < BASIS_BLOCKS) {
        int n = bid * 256 + threadIdx.x;
        if (n >= BASIS_ITEMS) return;
        int o = n / (2 * T_NO);
        int r = n % (2 * T_NO);
        int c = r / T_NO;
        int t = r % T_NO;
        int s = o / H_NO;
        int h = o % H_NO;
        float raw = 5.0f * logf((float)t + 1.0f);
        float acc = 0.f;
#pragma unroll
        for (int b = 0; b < COS_NO; ++b) {
            float phi = HALF_PI_F * (float)b;
            float dlt = raw - phi;
            if (raw >= phi - PI_F && raw <= phi + PI_F) {
                float bas = 0.5f * cosf(dlt) + 0.5f;
                acc += W_conv[(o * 2 + c) * COS_NO + b] * bas;
            }
        }
        g_kern2[(((s * 2 + c) * 8 + (h >> 1)) * T_NO + t) * 2 + (h & 1)] = acc;
        if (out_kern) out_kern[o * 2 * T_NO + c * T_NO + (T_NO - 1 - t)] = acc;
    } else {
        int i = (bid - BASIS_BLOCKS) * 256 + threadIdx.x;
        if (i >= ZERO_ITEMS) return;
        int ch = i / ZERO_PER_CH;
        int r = i % ZERO_PER_CH;
        int x = (r < 199) ? r : (199 + T_DATA) + (r - 199);
        g_S[(long)ch * S_PITCH + x] = 0.f;
    }
}

// ---------------- GEMM1 v3: staged A, 2 t/thread, f32x2 sub-pairs ----------------
// grid (196, 2): blockIdx.y = phase.  128 threads, t-tile 256.
__global__ __launch_bounds__(128) void gemm1_kernel(const float* __restrict__ Se,
                                                    const float* __restrict__ Si,
                                                    const float* __restrict__ Ce,
                                                    const float* __restrict__ Ci) {
    __shared__ __align__(16) float sA[256 * 36];   // [row][k-chunk 32, pad 36]
    __shared__ __align__(16) float sB[32 * 20];    // [k][sub] (pairs adjacent)
    const int tid = threadIdx.x;
    const int tB = blockIdx.x * 256;
    const int phase = blockIdx.y;
    const float* A = phase ? Si : Se;
    const float* B = phase ? Ci : Ce;
    const int K = phase ? I_NO : E_NO;

    ull acc2[10][2];
#pragma unroll
    for (int sp = 0; sp < 10; ++sp) { acc2[sp][0] = 0ull; acc2[sp][1] = 0ull; }

    const int nch = (K + 31) >> 5;
    for (int ch = 0; ch < nch; ++ch) {
        const int k0 = ch << 5;
        __syncthreads();
        // stage A: 256 rows x 32 k = 2048 float4, coalesced
#pragma unroll
        for (int it = 0; it < 16; ++it) {
            int i = it * 128 + tid;
            int r = i >> 3, q = i & 7;
            int t = tB + r, k = k0 + q * 4;
            float4 v = make_float4(0.f, 0.f, 0.f, 0.f);
            if (t < T_DATA && k < K)
                v = *reinterpret_cast<const float4*>(A + (long)t * K + k);
            *reinterpret_cast<float4*>(&sA[r * 36 + q * 4]) = v;
        }
        // stage B: 32 k x 20 subs
#pragma unroll
        for (int it = 0; it < 5; ++it) {
            int i = it * 128 + tid;
            int s = i >> 5, kk = i & 31;
            float v = (k0 + kk < K) ? B[s * K + k0 + kk] : 0.f;
            sB[kk * 20 + s] = v;
        }
        __syncthreads();
#pragma unroll
        for (int k4 = 0; k4 < 8; ++k4) {
            float4 a0 = *reinterpret_cast<const float4*>(&sA[tid * 36 + k4 * 4]);
            float4 a1 = *reinterpret_cast<const float4*>(&sA[(tid + 128) * 36 + k4 * 4]);
            ull ap0[4], ap1[4];
            ap0[0] = pack2(a0.x, a0.x); ap0[1] = pack2(a0.y, a0.y);
            ap0[2] = pack2(a0.z, a0.z); ap0[3] = pack2(a0.w, a0.w);
            ap1[0] = pack2(a1.x, a1.x); ap1[1] = pack2(a1.y, a1.y);
            ap1[2] = pack2(a1.z, a1.z); ap1[3] = pack2(a1.w, a1.w);
#pragma unroll
            for (int m = 0; m < 4; ++m) {
                const float* brow = &sB[(k4 * 4 + m) * 20];
#pragma unroll
                for (int s4 = 0; s4 < 5; ++s4) {
                    ulonglong2 b = *reinterpret_cast<const ulonglong2*>(brow + s4 * 4);
                    fma2(acc2[s4 * 2][0],     ap0[m], b.x);
                    fma2(acc2[s4 * 2 + 1][0], ap0[m], b.y);
                    fma2(acc2[s4 * 2][1],     ap1[m], b.x);
                    fma2(acc2[s4 * 2 + 1][1], ap1[m], b.y);
                }
            }
        }
    }
#pragma unroll
    for (int tt = 0; tt < 2; ++tt) {
        int t = tB + tt * 128 + tid;
        if (t < T_DATA) {
#pragma unroll
            for (int sp = 0; sp < 10; ++sp) {
                float2 v = unpack2(acc2[sp][tt]);
                g_S[(long)(2 * (2 * sp) + phase) * S_PITCH + 199 + t]     = v.x;
                g_S[(long)(2 * (2 * sp + 1) + phase) * S_PITCH + 199 + t] = v.y;
            }
        }
    }
}

// ---------------- fused conv (f32x2 h-pairs, d-step 4 = R4 measured-best) + MLP ----
__global__ __launch_bounds__(256, 2) void conv_mlp_kernel(const float* __restrict__ ff_w,
                                                          const float* __restrict__ ff_b,
                                                          const float* __restrict__ ff2_w,
                                                          const float* __restrict__ ff2_b,
                                                          const float* __restrict__ root_w) {
    __shared__ __align__(16) float sm[9104];
    float* sK = sm;                 // [c][h2(8)][d(200)][p(2)] = 6400
    float* sS = sm + 6400;          // [2][712]
    const int s = blockIdx.y;
    const int t0 = blockIdx.x * CONV_TT;
    const int tid = threadIdx.x;

    {
        const float4* gk4 = reinterpret_cast<const float4*>(g_kern2 + (long)s * 6400);
        float4* sK4 = reinterpret_cast<float4*>(sK);
        for (int i = tid; i < 1600; i += 256) sK4[i] = gk4[i];
        for (int i = tid; i < 2 * 178; i += 256) {
            int c = i / 178, x4 = i % 178;
            reinterpret_cast<float4*>(sS + c * 712)[x4] =
                *reinterpret_cast<const float4*>(g_S + (long)(2 * s + c) * S_PITCH + t0 + x4 * 4);
        }
    }
    __syncthreads();

    const int hg = tid >> 6;       // 4 h-groups (2 h-pairs each)
    const int tg = tid & 63;       // 8 t each
    const int tb = tg * 8;

    ull acc2[2][8];
#pragma unroll
    for (int h2 = 0; h2 < 2; ++h2)
#pragma unroll
        for (int j = 0; j < 8; ++j) acc2[h2][j] = 0ull;

    for (int c = 0; c < 2; ++c) {
        const float* kc = sK + (c * 8 + hg * 2) * (T_NO * 2);
        const float* sc = sS + c * 712;
#pragma unroll 2
        for (int d = 0; d < T_NO; d += 4) {
            ull kk2[2][4];
#pragma unroll
            for (int h2 = 0; h2 < 2; ++h2) {
                ulonglong2 kva = *reinterpret_cast<const ulonglong2*>(kc + h2 * (T_NO * 2) + d * 2);
                ulonglong2 kvb = *reinterpret_cast<const ulonglong2*>(kc + h2 * (T_NO * 2) + d * 2 + 4);
                kk2[h2][0] = kva.x; kk2[h2][1] = kva.y;
                kk2[h2][2] = kvb.x; kk2[h2][3] = kvb.y;
            }
            const int x0 = tb + 196 - d;           // sS index of S[t0+tb - d - 3]
            float w[12];
            float4 wa = *reinterpret_cast<const float4*>(sc + x0);
            float4 wb = *reinterpret_cast<const float4*>(sc + x0 + 4);
            float4 wc = *reinterpret_cast<const float4*>(sc + x0 + 8);
            w[0] = wa.x; w[1] = wa.y; w[2] = wa.z; w[3] = wa.w;
            w[4] = wb.x; w[5] = wb.y; w[6] = wb.z; w[7] = wb.w;
            w[8] = wc.x; w[9] = wc.y; w[10] = wc.z; w[11] = wc.w;
            ull wp[11];
#pragma unroll
            for (int x = 0; x < 11; ++x) wp[x] = pack2(w[x], w[x]);
#pragma unroll
            for (int h2 = 0; h2 < 2; ++h2)
#pragma unroll
                for (int m = 0; m < 4; ++m)
#pragma unroll
                    for (int j = 0; j < 8; ++j)
                        fma2(acc2[h2][j], kk2[h2][m], wp[j + 3 - m]);
        }
    }
    __syncthreads();

    float* sX  = sm;            // [16][528]
    float* sW1 = sm + 8448;
    float* sW2 = sm + 8704;
    float* sb1 = sm + 8960;
    float* sb2 = sm + 8976;
    float* sr  = sm + 8992;
#pragma unroll
    for (int h2 = 0; h2 < 2; ++h2) {
        float a0[8], a1[8];
#pragma unroll
        for (int j = 0; j < 8; ++j) {
            float2 v = unpack2(acc2[h2][j]);
            a0[j] = v.x > 0.f ? v.x : 0.01f * v.x;
            a1[j] = v.y > 0.f ? v.y : 0.01f * v.y;
        }
        int hb = hg * 4 + h2 * 2;
        *reinterpret_cast<float4*>(&sX[hb * 528 + tb])           = make_float4(a0[0], a0[1], a0[2], a0[3]);
        *reinterpret_cast<float4*>(&sX[hb * 528 + tb + 4])       = make_float4(a0[4], a0[5], a0[6], a0[7]);
        *reinterpret_cast<float4*>(&sX[(hb + 1) * 528 + tb])     = make_float4(a1[0], a1[1], a1[2], a1[3]);
        *reinterpret_cast<float4*>(&sX[(hb + 1) * 528 + tb + 4]) = make_float4(a1[4], a1[5], a1[6], a1[7]);
    }
    sW1[tid] = ff_w[s * 256 + tid];
    sW2[tid] = ff2_w[s * 256 + tid];
    if (tid < 16) {
        sb1[tid] = ff_b[s * 16 + tid];
        sb2[tid] = ff2_b[s * 16 + tid];
        sr[tid]  = root_w[s * 16 + tid];
    }
    __syncthreads();

#pragma unroll
    for (int tt = 0; tt < 2; ++tt) {
        int tl = tid + tt * 256;
        int t = t0 + tl;
        if (t < T_DATA) {
            float x[16];
#pragma unroll
            for (int i = 0; i < 16; ++i) x[i] = sX[i * 528 + tl];
            float h1[16];
#pragma unroll
            for (int o = 0; o < 16; ++o) {
                float4 w0 = *reinterpret_cast<const float4*>(&sW1[o * 16]);
                float4 w1 = *reinterpret_cast<const float4*>(&sW1[o * 16 + 4]);
                float4 w2 = *reinterpret_cast<const float4*>(&sW1[o * 16 + 8]);
                float4 w3 = *reinterpret_cast<const float4*>(&sW1[o * 16 + 12]);
                float a = sb1[o];
                a += w0.x * x[0] + w0.y * x[1] + w0.z * x[2] + w0.w * x[3];
                a += w1.x * x[4] + w1.y * x[5] + w1.z * x[6] + w1.w * x[7];
                a += w2.x * x[8] + w2.y * x[9] + w2.z * x[10] + w2.w * x[11];
                a += w3.x * x[12] + w3.y * x[13] + w3.z * x[14] + w3.w * x[15];
                h1[o] = a > 0.f ? a : 0.01f * a;
            }
            float part = 0.f;
#pragma unroll
            for (int o = 0; o < 16; ++o) {
                float4 w0 = *reinterpret_cast<const float4*>(&sW2[o * 16]);
                float4 w1 = *reinterpret_cast<const float4*>(&sW2[o * 16 + 4]);
                float4 w2 = *reinterpret_cast<const float4*>(&sW2[o * 16 + 8]);
                float4 w3 = *reinterpret_cast<const float4*>(&sW2[o * 16 + 12]);
                float a = sb2[o];
                a += w0.x * h1[0] + w0.y * h1[1] + w0.z * h1[2] + w0.w * h1[3];
                a += w1.x * h1[4] + w1.y * h1[5] + w1.z * h1[6] + w1.w * h1[7];
                a += w2.x * h1[8] + w2.y * h1[9] + w2.z * h1[10] + w2.w * h1[11];
                a += w3.x * h1[12] + w3.y * h1[13] + w3.z * h1[14] + w3.w * h1[15];
                float h2v = a > 0.f ? a : 0.01f * a;
                part += sr[o] * h2v;
            }
            g_partial[(long)s * T_DATA + t] = part;
        }
    }
}

// ---------------- reduce over subunits + bias (float4) ----------------
__global__ void reduce_kernel(const float* __restrict__ root_b,
                              const float* __restrict__ V_o,
                              float* __restrict__ out) {
    int i = blockIdx.x * blockDim.x + threadIdx.x;    // float4 index
    if (i >= T_DATA / 4) return;
    float bias = root_b[0] + V_o[0];
    float4 acc = make_float4(bias, bias, bias, bias);
#pragma unroll
    for (int s = 0; s < SUB_NO; ++s) {
        float4 v = *reinterpret_cast<const float4*>(g_partial + (long)s * T_DATA + i * 4);
        acc.x += v.x; acc.y += v.y; acc.z += v.z; acc.w += v.w;
    }
    *reinterpret_cast<float4*>(out + i * 4) = acc;
}

// ---------------- launch ----------------
extern "C" void kernel_launch(void* const* d_in, const int* in_sizes, int n_in,
                              void* d_out, int out_size) {
    const float* S_e    = (const float*)d_in[0];
    const float* S_i    = (const float*)d_in[1];
    const float* C_e    = (const float*)d_in[2];
    const float* C_i    = (const float*)d_in[3];
    const float* W_conv = (const float*)d_in[4];
    const float* ff_w   = (const float*)d_in[5];
    const float* ff_b   = (const float*)d_in[6];
    const float* ff2_w  = (const float*)d_in[7];
    const float* ff2_b  = (const float*)d_in[8];
    const float* root_w = (const float*)d_in[9];
    const float* root_b = (const float*)d_in[10];
    const float* V_o    = (const float*)d_in[11];
    float* out = (float*)d_out;

    float* kern_out = (out_size >= T_DATA + SUB_NO * H_NO * 2 * T_NO) ? (out + T_DATA) : nullptr;
    prep_kernel<<<BASIS_BLOCKS + ZERO_BLOCKS, 256>>>(W_conv, kern_out);

    dim3 g1((T_DATA + 255) / 256, 2);
    gemm1_kernel<<<g1, 128>>>(S_e, S_i, C_e, C_i);

    dim3 grid((T_DATA + CONV_TT - 1) / CONV_TT, SUB_NO);
    conv_mlp_kernel<<<grid, 256>>>(ff_w, ff_b, ff2_w, ff2_b, root_w);

    reduce_kernel<<<(T_DATA / 4 + 255) / 256, 256>>>(root_b, V_o, out);
}

// round 8
// speedup vs baseline: 1.1288x; 1.1288x over previous
#include <cuda_runtime.h>
#include <math.h>

#define T_DATA   50000
#define E_NO     1000
#define I_NO     200
#define SUB_NO   20
#define H_NO     16
#define T_NO     200
#define COS_NO   20

#define S_PITCH  50432
#define CONV_TT  512
#define PI_F     3.14159265358979323846f
#define HALF_PI_F 1.57079632679489662f

typedef unsigned long long ull;

__device__ __forceinline__ ull pack2(float lo, float hi) {
    ull r; asm("mov.b64 %0, {%1, %2};" : "=l"(r) : "f"(lo), "f"(hi)); return r;
}
__device__ __forceinline__ void fma2(ull& d, ull a, ull b) {
    asm("fma.rn.f32x2 %0, %1, %2, %0;" : "+l"(d) : "l"(a), "l"(b));
}
__device__ __forceinline__ float2 unpack2(ull v) {
    float2 f; asm("mov.b64 {%0, %1}, %2;" : "=f"(f.x), "=f"(f.y) : "l"(v)); return f;
}
__device__ __forceinline__ void cp_async16(unsigned dst, const void* src) {
    asm volatile("cp.async.cg.shared.global [%0], [%1], 16;" :: "r"(dst), "l"(src));
}
__device__ __forceinline__ void cp_commit() { asm volatile("cp.async.commit_group;"); }
__device__ __forceinline__ void cp_wait1()  { asm volatile("cp.async.wait_group 1;"); }
__device__ __forceinline__ void cp_wait0()  { asm volatile("cp.async.wait_group 0;"); }

// ---------------- device scratch ----------------
__device__ float g_S[2 * SUB_NO * S_PITCH];          // [40][S_PITCH], pad 199 zeros
__device__ float g_kern2[SUB_NO * 2 * H_NO * T_NO];  // [s][c][h/2][d][h%2]
__device__ float g_partial[SUB_NO * T_DATA];

// ---------------- merged: basis*W_conv (+ flipped copy) AND g_S pad zeroing ----------------
#define BASIS_ITEMS (SUB_NO * H_NO * 2 * T_NO)
#define BASIS_BLOCKS 500
#define ZERO_PER_CH (199 + (S_PITCH - (199 + T_DATA)))   // 432
#define ZERO_ITEMS (2 * SUB_NO * ZERO_PER_CH)
#define ZERO_BLOCKS ((ZERO_ITEMS + 255) / 256)

__global__ void prep_kernel(const float* __restrict__ W_conv,
                            float* __restrict__ out_kern /* may be null */) {
    int bid = blockIdx.x;
    if (bid < BASIS_BLOCKS) {
        int n = bid * 256 + threadIdx.x;
        if (n >= BASIS_ITEMS) return;
        int o = n / (2 * T_NO);
        int r = n % (2 * T_NO);
        int c = r / T_NO;
        int t = r % T_NO;
        int s = o / H_NO;
        int h = o % H_NO;
        float raw = 5.0f * logf((float)t + 1.0f);
        float acc = 0.f;
#pragma unroll
        for (int b = 0; b < COS_NO; ++b) {
            float phi = HALF_PI_F * (float)b;
            float dlt = raw - phi;
            if (raw >= phi - PI_F && raw <= phi + PI_F) {
                float bas = 0.5f * cosf(dlt) + 0.5f;
                acc += W_conv[(o * 2 + c) * COS_NO + b] * bas;
            }
        }
        g_kern2[(((s * 2 + c) * 8 + (h >> 1)) * T_NO + t) * 2 + (h & 1)] = acc;
        if (out_kern) out_kern[o * 2 * T_NO + c * T_NO + (T_NO - 1 - t)] = acc;
    } else {
        int i = (bid - BASIS_BLOCKS) * 256 + threadIdx.x;
        if (i >= ZERO_ITEMS) return;
        int ch = i / ZERO_PER_CH;
        int r = i % ZERO_PER_CH;
        int x = (r < 199) ? r : (199 + T_DATA) + (r - 199);
        g_S[(long)ch * S_PITCH + x] = 0.f;
    }
}

// ---------------- GEMM1 v4: cp.async double-buffered pipeline ----------------
// grid (391, 2). 128 threads, 1 t-row/thread, K-chunk 20 (divides 1000 and 200).
#define GK       20
#define GROWS    128
#define SA_STR   28                 // pad 20 -> 28 floats (2-way max LDS.128 conflict)
__global__ __launch_bounds__(128) void gemm1_kernel(const float* __restrict__ Se,
                                                    const float* __restrict__ Si,
                                                    const float* __restrict__ Ce,
                                                    const float* __restrict__ Ci) {
    __shared__ __align__(16) float sA[2][GROWS * SA_STR];   // 28 KB
    __shared__ __align__(16) float sB[2][GK * 20];          // 3.2 KB  [k][sub]
    const int tid = threadIdx.x;
    const int tB = blockIdx.x * GROWS;
    const int phase = blockIdx.y;
    const float* A = phase ? Si : Se;
    const float* B = phase ? Ci : Ce;
    const int K = phase ? I_NO : E_NO;
    const int nch = K / GK;          // 50 or 10

    const unsigned saBase = (unsigned)__cvta_generic_to_shared(&sA[0][0]);

    ull acc2[10];
#pragma unroll
    for (int sp = 0; sp < 10; ++sp) acc2[sp] = 0ull;

    // ---- prologue: prefetch A chunk 0 (buf 0), B chunk 0 into sB[0] ----
    {
#pragma unroll
        for (int it = 0; it < 5; ++it) {
            int i = it * 128 + tid;          // 640 f4: r = i/5, q = i%5
            int r = i / 5, q = i % 5;
            int t = tB + r; if (t >= T_DATA) t = T_DATA - 1;
            cp_async16(saBase + (unsigned)((r * SA_STR + q * 4) * 4),
                       A + (long)t * K + q * 4);
        }
        cp_commit();
#pragma unroll
        for (int j = 0; j < 4; ++j) {
            int i = j * 128 + tid;
            if (i < GK * 20) {
                int su = i / GK, kk = i % GK;
                sB[0][kk * 20 + su] = B[su * K + kk];
            }
        }
    }

    for (int ch = 0; ch < nch; ++ch) {
        const int buf = ch & 1;
        float breg[4];
        bool more = (ch + 1 < nch);
        if (more) {
            const int k0n = (ch + 1) * GK;
            // B chunk ch+1 -> regs (LDG issued now, consumed after compute)
#pragma unroll
            for (int j = 0; j < 4; ++j) {
                int i = j * 128 + tid;
                breg[j] = (i < GK * 20) ? B[(i / GK) * K + k0n + (i % GK)] : 0.f;
            }
            // A chunk ch+1 -> other buffer via cp.async
            const unsigned dstB = saBase + (unsigned)((buf ^ 1) * GROWS * SA_STR * 4);
#pragma unroll
            for (int it = 0; it < 5; ++it) {
                int i = it * 128 + tid;
                int r = i / 5, q = i % 5;
                int t = tB + r; if (t >= T_DATA) t = T_DATA - 1;
                cp_async16(dstB + (unsigned)((r * SA_STR + q * 4) * 4),
                           A + (long)t * K + k0n + q * 4);
            }
            cp_commit();
            cp_wait1();            // chunk ch's group has landed
        } else {
            cp_wait0();
        }
        __syncthreads();

        // ---- compute chunk ch ----
        const float* myrow = &sA[buf][tid * SA_STR];
        const float* bb = &sB[buf][0];
#pragma unroll
        for (int k4 = 0; k4 < GK / 4; ++k4) {
            float4 a = *reinterpret_cast<const float4*>(myrow + k4 * 4);
            ull ap[4];
            ap[0] = pack2(a.x, a.x); ap[1] = pack2(a.y, a.y);
            ap[2] = pack2(a.z, a.z); ap[3] = pack2(a.w, a.w);
#pragma unroll
            for (int m = 0; m < 4; ++m) {
                const float* brow = bb + (k4 * 4 + m) * 20;
#pragma unroll
                for (int s4 = 0; s4 < 5; ++s4) {
                    ulonglong2 b = *reinterpret_cast<const ulonglong2*>(brow + s4 * 4);
                    fma2(acc2[s4 * 2],     ap[m], b.x);
                    fma2(acc2[s4 * 2 + 1], ap[m], b.y);
                }
            }
        }

        if (more) {
            // store prefetched B regs into the other buffer
#pragma unroll
            for (int j = 0; j < 4; ++j) {
                int i = j * 128 + tid;
                if (i < GK * 20) sB[buf ^ 1][(i % GK) * 20 + (i / GK)] = breg[j];
            }
        }
        __syncthreads();           // buffer reuse + sB visibility
    }

    const int t = tB + tid;
    if (t < T_DATA) {
#pragma unroll
        for (int sp = 0; sp < 10; ++sp) {
            float2 v = unpack2(acc2[sp]);
            g_S[(long)(2 * (2 * sp) + phase) * S_PITCH + 199 + t]     = v.x;
            g_S[(long)(2 * (2 * sp + 1) + phase) * S_PITCH + 199 + t] = v.y;
        }
    }
}

// ---------------- fused conv (f32x2 h-pairs, d-step 4 = measured-best) + MLP ----
__global__ __launch_bounds__(256, 2) void conv_mlp_kernel(const float* __restrict__ ff_w,
                                                          const float* __restrict__ ff_b,
                                                          const float* __restrict__ ff2_w,
                                                          const float* __restrict__ ff2_b,
                                                          const float* __restrict__ root_w) {
    __shared__ __align__(16) float sm[9104];
    float* sK = sm;                 // [c][h2(8)][d(200)][p(2)] = 6400
    float* sS = sm + 6400;          // [2][712]
    const int s = blockIdx.y;
    const int t0 = blockIdx.x * CONV_TT;
    const int tid = threadIdx.x;

    {
        const float4* gk4 = reinterpret_cast<const float4*>(g_kern2 + (long)s * 6400);
        float4* sK4 = reinterpret_cast<float4*>(sK);
        for (int i = tid; i < 1600; i += 256) sK4[i] = gk4[i];
        for (int i = tid; i < 2 * 178; i += 256) {
            int c = i / 178, x4 = i % 178;
            reinterpret_cast<float4*>(sS + c * 712)[x4] =
                *reinterpret_cast<const float4*>(g_S + (long)(2 * s + c) * S_PITCH + t0 + x4 * 4);
        }
    }
    __syncthreads();

    const int hg = tid >> 6;
    const int tg = tid & 63;
    const int tb = tg * 8;

    ull acc2[2][8];
#pragma unroll
    for (int h2 = 0; h2 < 2; ++h2)
#pragma unroll
        for (int j = 0; j < 8; ++j) acc2[h2][j] = 0ull;

    for (int c = 0; c < 2; ++c) {
        const float* kc = sK + (c * 8 + hg * 2) * (T_NO * 2);
        const float* sc = sS + c * 712;
#pragma unroll 2
        for (int d = 0; d < T_NO; d += 4) {
            ull kk2[2][4];
#pragma unroll
            for (int h2 = 0; h2 < 2; ++h2) {
                ulonglong2 kva = *reinterpret_cast<const ulonglong2*>(kc + h2 * (T_NO * 2) + d * 2);
                ulonglong2 kvb = *reinterpret_cast<const ulonglong2*>(kc + h2 * (T_NO * 2) + d * 2 + 4);
                kk2[h2][0] = kva.x; kk2[h2][1] = kva.y;
                kk2[h2][2] = kvb.x; kk2[h2][3] = kvb.y;
            }
            const int x0 = tb + 196 - d;
            float w[12];
            float4 wa = *reinterpret_cast<const float4*>(sc + x0);
            float4 wb = *reinterpret_cast<const float4*>(sc + x0 + 4);
            float4 wc = *reinterpret_cast<const float4*>(sc + x0 + 8);
            w[0] = wa.x; w[1] = wa.y; w[2] = wa.z; w[3] = wa.w;
            w[4] = wb.x; w[5] = wb.y; w[6] = wb.z; w[7] = wb.w;
            w[8] = wc.x; w[9] = wc.y; w[10] = wc.z; w[11] = wc.w;
            ull wp[11];
#pragma unroll
            for (int x = 0; x < 11; ++x) wp[x] = pack2(w[x], w[x]);
#pragma unroll
            for (int h2 = 0; h2 < 2; ++h2)
#pragma unroll
                for (int m = 0; m < 4; ++m)
#pragma unroll
                    for (int j = 0; j < 8; ++j)
                        fma2(acc2[h2][j], kk2[h2][m], wp[j + 3 - m]);
        }
    }
    __syncthreads();

    float* sX  = sm;            // [16][528]
    float* sW1 = sm + 8448;
    float* sW2 = sm + 8704;
    float* sb1 = sm + 8960;
    float* sb2 = sm + 8976;
    float* sr  = sm + 8992;
#pragma unroll
    for (int h2 = 0; h2 < 2; ++h2) {
        float a0[8], a1[8];
#pragma unroll
        for (int j = 0; j < 8; ++j) {
            float2 v = unpack2(acc2[h2][j]);
            a0[j] = v.x > 0.f ? v.x : 0.01f * v.x;
            a1[j] = v.y > 0.f ? v.y : 0.01f * v.y;
        }
        int hb = hg * 4 + h2 * 2;
        *reinterpret_cast<float4*>(&sX[hb * 528 + tb])           = make_float4(a0[0], a0[1], a0[2], a0[3]);
        *reinterpret_cast<float4*>(&sX[hb * 528 + tb + 4])       = make_float4(a0[4], a0[5], a0[6], a0[7]);
        *reinterpret_cast<float4*>(&sX[(hb + 1) * 528 + tb])     = make_float4(a1[0], a1[1], a1[2], a1[3]);
        *reinterpret_cast<float4*>(&sX[(hb + 1) * 528 + tb + 4]) = make_float4(a1[4], a1[5], a1[6], a1[7]);
    }
    sW1[tid] = ff_w[s * 256 + tid];
    sW2[tid] = ff2_w[s * 256 + tid];
    if (tid < 16) {
        sb1[tid] = ff_b[s * 16 + tid];
        sb2[tid] = ff2_b[s * 16 + tid];
        sr[tid]  = root_w[s * 16 + tid];
    }
    __syncthreads();

#pragma unroll
    for (int tt = 0; tt < 2; ++tt) {
        int tl = tid + tt * 256;
        int t = t0 + tl;
        if (t < T_DATA) {
            float x[16];
#pragma unroll
            for (int i = 0; i < 16; ++i) x[i] = sX[i * 528 + tl];
            float h1[16];
#pragma unroll
            for (int o = 0; o < 16; ++o) {
                float4 w0 = *reinterpret_cast<const float4*>(&sW1[o * 16]);
                float4 w1 = *reinterpret_cast<const float4*>(&sW1[o * 16 + 4]);
                float4 w2 = *reinterpret_cast<const float4*>(&sW1[o * 16 + 8]);
                float4 w3 = *reinterpret_cast<const float4*>(&sW1[o * 16 + 12]);
                float a = sb1[o];
                a += w0.x * x[0] + w0.y * x[1] + w0.z * x[2] + w0.w * x[3];
                a += w1.x * x[4] + w1.y * x[5] + w1.z * x[6] + w1.w * x[7];
                a += w2.x * x[8] + w2.y * x[9] + w2.z * x[10] + w2.w * x[11];
                a += w3.x * x[12] + w3.y * x[13] + w3.z * x[14] + w3.w * x[15];
                h1[o] = a > 0.f ? a : 0.01f * a;
            }
            float part = 0.f;
#pragma unroll
            for (int o = 0; o < 16; ++o) {
                float4 w0 = *reinterpret_cast<const float4*>(&sW2[o * 16]);
                float4 w1 = *reinterpret_cast<const float4*>(&sW2[o * 16 + 4]);
                float4 w2 = *reinterpret_cast<const float4*>(&sW2[o * 16 + 8]);
                float4 w3 = *reinterpret_cast<const float4*>(&sW2[o * 16 + 12]);
                float a = sb2[o];
                a += w0.x * h1[0] + w0.y * h1[1] + w0.z * h1[2] + w0.w * h1[3];
                a += w1.x * h1[4] + w1.y * h1[5] + w1.z * h1[6] + w1.w * h1[7];
                a += w2.x * h1[8] + w2.y * h1[9] + w2.z * h1[10] + w2.w * h1[11];
                a += w3.x * h1[12] + w3.y * h1[13] + w3.z * h1[14] + w3.w * h1[15];
                float h2v = a > 0.f ? a : 0.01f * a;
                part += sr[o] * h2v;
            }
            g_partial[(long)s * T_DATA + t] = part;
        }
    }
}

// ---------------- reduce over subunits + bias (float4) ----------------
__global__ void reduce_kernel(const float* __restrict__ root_b,
                              const float* __restrict__ V_o,
                              float* __restrict__ out) {
    int i = blockIdx.x * blockDim.x + threadIdx.x;
    if (i >= T_DATA / 4) return;
    float bias = root_b[0] + V_o[0];
    float4 acc = make_float4(bias, bias, bias, bias);
#pragma unroll
    for (int s = 0; s < SUB_NO; ++s) {
        float4 v = *reinterpret_cast<const float4*>(g_partial + (long)s * T_DATA + i * 4);
        acc.x += v.x; acc.y += v.y; acc.z += v.z; acc.w += v.w;
    }
    *reinterpret_cast<float4*>(out + i * 4) = acc;
}

// ---------------- launch ----------------
extern "C" void kernel_launch(void* const* d_in, const int* in_sizes, int n_in,
                              void* d_out, int out_size) {
    const float* S_e    = (const float*)d_in[0];
    const float* S_i    = (const float*)d_in[1];
    const float* C_e    = (const float*)d_in[2];
    const float* C_i    = (const float*)d_in[3];
    const float* W_conv = (const float*)d_in[4];
    const float* ff_w   = (const float*)d_in[5];
    const float* ff_b   = (const float*)d_in[6];
    const float* ff2_w  = (const float*)d_in[7];
    const float* ff2_b  = (const float*)d_in[8];
    const float* root_w = (const float*)d_in[9];
    const float* root_b = (const float*)d_in[10];
    const float* V_o    = (const float*)d_in[11];
    float* out = (float*)d_out;

    float* kern_out = (out_size >= T_DATA + SUB_NO * H_NO * 2 * T_NO) ? (out + T_DATA) : nullptr;
    prep_kernel<<<BASIS_BLOCKS + ZERO_BLOCKS, 256>>>(W_conv, kern_out);

    dim3 g1((T_DATA + GROWS - 1) / GROWS, 2);
    gemm1_kernel<<<g1, 128>>>(S_e, S_i, C_e, C_i);

    dim3 grid((T_DATA + CONV_TT - 1) / CONV_TT, SUB_NO);
    conv_mlp_kernel<<<grid, 256>>>(ff_w, ff_b, ff2_w, ff2_b, root_w);

    reduce_kernel<<<(T_DATA / 4 + 255) / 256, 256>>>(root_b, V_o, out);
}